// round 17
// baseline (speedup 1.0000x reference)
#include <cuda_runtime.h>

#define NPB 15    // prob bins
#define NC  8     // classes
#define NNB 9     // neighbor bins (3x3)
#define HH  512
#define WW  512
#define TW  64    // tile width  (warp covers one row, 2 px/lane)
#define TH  16    // tile height (= warps per block)
#define NTHREADS 512
#define HWD 68         // halo width: 2 pad left + 64 + 2 pad right
#define HHT (TH + 2)   // 18 halo rows
#define NPAIR (HWD / 2) // 34 pixel-pairs per halo row
#define NPIX (HHT * NPAIR) // 612 pairs
#define TBL (NNB * NPB)    // 135 entries per class

typedef unsigned long long ull;

__device__ __forceinline__ ull f2add(ull a, ull b) {
    ull r;
    asm("add.rn.f32x2 %0, %1, %2;" : "=l"(r) : "l"(a), "l"(b));
    return r;
}
__device__ __forceinline__ float lo32(ull u) { return __uint_as_float((unsigned)u); }
__device__ __forceinline__ float hi32(ull u) { return __uint_as_float((unsigned)(u >> 32)); }

__device__ __forceinline__ float frcp_fast(float x) {
    float r;
    asm("rcp.approx.f32 %0, %1;" : "=f"(r) : "f"(x));
    return r;
}

__device__ __forceinline__ int bin_lbn(float s9) {
    // fast path: floor(RN(RN(s/9)*9)) == floor(s) unless s is within ~2.5 ulp
    // of an integer; 1e-5 window guards the rare exact double-rounded path.
    const int ib = (int)s9;                    // trunc == floor (s9 >= 0)
    const float fr = s9 - (float)ib;
    int lbn = min(ib, NNB - 1);
    if ((fr < 1e-5f) | (fr > 0.99999f)) {
        lbn = min(max((int)floorf(__fmul_rn(__fdiv_rn(s9, 9.0f), 9.0f)), 0), NNB - 1);
    }
    return lbn;
}

__global__ __launch_bounds__(NTHREADS, 4) void nectar_kernel(
    const float* __restrict__ logits,
    const float* __restrict__ vf,
    float* __restrict__ out)
{
    // Parity/half-split planes: lane-consecutive pair index -> 16B lane stride
    // -> structurally conflict-free .128 ops, no swizzle math, immediate offsets.
    __shared__ ulonglong2 s_e[2][NPIX];   // even-x pixels, channel halves 0/1
    __shared__ ulonglong2 s_o[2][NPIX];   // odd-x pixels
    __shared__ float s_vf[NC * TBL];

    const int t  = threadIdx.x;
    const int b  = blockIdx.z;
    const int bx = blockIdx.x * TW;
    const int by = blockIdx.y * TH;

    for (int i = t; i < NC * TBL; i += NTHREADS) s_vf[i] = vf[i];

    const long plane = (long)HH * WW;
    const float* lbase = logits + (long)b * NC * plane;

    // Stage 1: halo softmax by even-aligned pixel PAIRS; 2-px pad makes the
    // pair uniformly inside/outside the image in x -> one predicate.
    // Softmax is shift-invariant and logits are O(1): skip the max-subtract.
    for (int i = t; i < NPIX; i += NTHREADS) {
        const int hy = i / NPAIR;
        const int ip = i - hy * NPAIR;
        const int gy  = by + hy - 1;
        const int gx0 = bx - 2 + 2 * ip;       // even
        float4 a0, c0, a1, c1;
        if (gy >= 0 && gy < HH && gx0 >= 0 && gx0 < WW) {
            float2 w[NC];
            const float* q = lbase + (long)gy * WW + gx0;
#pragma unroll
            for (int k = 0; k < NC; k++)
                w[k] = *(const float2*)(q + k * plane);
            {   // softmax px0 (even)
                float v[NC];
#pragma unroll
                for (int k = 0; k < NC; k++) v[k] = __expf(w[k].x);
                const float sm = ((v[0] + v[1]) + (v[2] + v[3]))
                               + ((v[4] + v[5]) + (v[6] + v[7]));
                const float inv = frcp_fast(sm);
                a0 = make_float4(v[0] * inv, v[1] * inv, v[2] * inv, v[3] * inv);
                c0 = make_float4(v[4] * inv, v[5] * inv, v[6] * inv, v[7] * inv);
            }
            {   // softmax px1 (odd)
                float v[NC];
#pragma unroll
                for (int k = 0; k < NC; k++) v[k] = __expf(w[k].y);
                const float sm = ((v[0] + v[1]) + (v[2] + v[3]))
                               + ((v[4] + v[5]) + (v[6] + v[7]));
                const float inv = frcp_fast(sm);
                a1 = make_float4(v[0] * inv, v[1] * inv, v[2] * inv, v[3] * inv);
                c1 = make_float4(v[4] * inv, v[5] * inv, v[6] * inv, v[7] * inv);
            }
        } else {
            a0 = make_float4(0.f, 0.f, 0.f, 0.f);
            c0 = a0; a1 = a0; c1 = a0;
        }
        *(float4*)&s_e[0][i] = a0;
        *(float4*)&s_e[1][i] = c0;
        *(float4*)&s_o[0][i] = a1;
        *(float4*)&s_o[1][i] = c1;
    }
    __syncthreads();

    // Stage 2: per-lane PAIR of outputs. px0 even (halo x 2l+2), px1 odd (2l+3)
    // -> both at pair index q = wy*NPAIR + l + 1 in their parity planes.
    const int lane = t & 31;
    const int wy   = t >> 5;                  // 0..15 output row in tile
    const int gy   = by + wy;
    const int gx0  = bx + 2 * lane;
    const int q    = wy * NPAIR + lane + 1;   // pair index, top halo row
    const bool e0  = (lane == 0);
    const bool e31 = (lane == 31);
    const int qe   = wy * NPAIR + (e0 ? 0 : NPAIR - 1); // edge pair (lanes 0/31)

    // deferred-gather state: 8-bit table code (lbn*15+pbn, <=134) per channel
    ull pk0 = 0, pk1 = 0;
    float s0 = 0.f, s1 = 0.f;

#pragma unroll
    for (int h = 0; h < 2; h++) {             // channel halves: 4h..4h+3
        // column A (even) : rows wy, wy+1 (center), wy+2
        const ulonglong2 rA0  = s_e[h][q];
        const ulonglong2 cenA = s_e[h][q + NPAIR];
        const ulonglong2 rA2  = s_e[h][q + 2 * NPAIR];
        const ull csA0 = f2add(f2add(rA0.x, cenA.x), rA2.x);
        const ull csA1 = f2add(f2add(rA0.y, cenA.y), rA2.y);
        // column B (odd)
        const ulonglong2 rB0  = s_o[h][q];
        const ulonglong2 cenB = s_o[h][q + NPAIR];
        const ulonglong2 rB2  = s_o[h][q + 2 * NPAIR];
        const ull csB0 = f2add(f2add(rB0.x, cenB.x), rB2.x);
        const ull csB1 = f2add(f2add(rB0.y, cenB.y), rB2.y);
        // edge halo column: lane 0 needs odd pair 0 (x=1); lane 31 even pair 33 (x=66)
        ull csE0 = 0, csE1 = 0;
        if (e0) {
            const ulonglong2 h0 = s_o[h][qe];
            const ulonglong2 h1 = s_o[h][qe + NPAIR];
            const ulonglong2 h2 = s_o[h][qe + 2 * NPAIR];
            csE0 = f2add(f2add(h0.x, h1.x), h2.x);
            csE1 = f2add(f2add(h0.y, h1.y), h2.y);
        }
        if (e31) {
            const ulonglong2 h0 = s_e[h][qe];
            const ulonglong2 h1 = s_e[h][qe + NPAIR];
            const ulonglong2 h2 = s_e[h][qe + 2 * NPAIR];
            csE0 = f2add(f2add(h0.x, h1.x), h2.x);
            csE1 = f2add(f2add(h0.y, h1.y), h2.y);
        }
        // shared middle sum A+B (packed)
        const ull tm0 = f2add(csA0, csB0);
        const ull tm1 = f2add(csA1, csB1);

        const float csAf[4] = {lo32(csA0), hi32(csA0), lo32(csA1), hi32(csA1)};
        const float csBf[4] = {lo32(csB0), hi32(csB0), lo32(csB1), hi32(csB1)};
        const float csEf[4] = {lo32(csE0), hi32(csE0), lo32(csE1), hi32(csE1)};
        const float tmf[4]  = {lo32(tm0),  hi32(tm0),  lo32(tm1),  hi32(tm1)};
        const float pc0[4]  = {lo32(cenA.x), hi32(cenA.x), lo32(cenA.y), hi32(cenA.y)};
        const float pc1[4]  = {lo32(cenB.x), hi32(cenB.x), lo32(cenB.y), hi32(cenB.y)};

#pragma unroll
        for (int j = 0; j < 4; j++) {
            float lft = __shfl_up_sync(0xffffffffu, csBf[j], 1);   // lane-1 colB
            float rgt = __shfl_down_sync(0xffffffffu, csAf[j], 1); // lane+1 colA
            if (e0)  lft = csEf[j];
            if (e31) rgt = csEf[j];
            const float n0 = lft + tmf[j];        // 3x3 sum, px0
            const float n1 = tmf[j] + rgt;        // 3x3 sum, px1
            const int c = 4 * h + j;
            const int pb0 = min((int)(pc0[j] * 15.0f), NPB - 1);   // p >= 0
            const int pb1 = min((int)(pc1[j] * 15.0f), NPB - 1);
            const int code0 = bin_lbn(n0) * NPB + pb0;             // 0..134
            const int code1 = bin_lbn(n1) * NPB + pb1;
            s0 += s_vf[c * TBL + code0];
            s1 += s_vf[c * TBL + code1];
            pk0 |= (ull)code0 << (8 * c);
            pk1 |= (ull)code1 << (8 * c);
        }
    }

    if (s0 == 0.f) s0 = 1.f;
    if (s1 == 0.f) s1 = 1.f;
    const float i0 = frcp_fast(s0);   // continuous path: no binning downstream
    const float i1 = frcp_fast(s1);

    float* obase = out + (long)b * NC * plane + (long)gy * WW + gx0;
#pragma unroll
    for (int c = 0; c < NC; c++) {    // re-gather from packed codes and write
        const int code0 = (int)(pk0 >> (8 * c)) & 255;
        const int code1 = (int)(pk1 >> (8 * c)) & 255;
        float2 o;
        o.x = s_vf[c * TBL + code0] * i0;
        o.y = s_vf[c * TBL + code1] * i1;
        *(float2*)(obase + c * plane) = o;
    }
}

extern "C" void kernel_launch(void* const* d_in, const int* in_sizes, int n_in,
                              void* d_out, int out_size)
{
    const float* logits = (const float*)d_in[0];
    const float* vf     = (const float*)d_in[1];
    float* out          = (float*)d_out;

    dim3 grid(WW / TW, HH / TH, 16 /*B*/);
    nectar_kernel<<<grid, NTHREADS>>>(logits, vf, out);
}